// round 3
// baseline (speedup 1.0000x reference)
#include <cuda_runtime.h>
#include <cuda_bf16.h>
#include <math.h>

// Problem constants
#define B_  64
#define T_  512
#define I_  512
#define H_  1024
#define G4  4096           // 4*H
#define BH  (B_*H_)        // 65536
#define BK  32
#define NSTAGE (H_/BK)     // 32

typedef unsigned long long u64;
typedef unsigned int u32;

// ---------------------------------------------------------------------------
// Device scratch
// ---------------------------------------------------------------------------
__device__ float g_xp[(size_t)2 * T_ * B_ * G4];     // xp[dir][t][b][g]  (1 GiB)
__device__ float g_wTd[2][H_][2 * G4];               // w_hh transposed + duplicated:
                                                     // [dir][k][2n]=[2n+1]=w[n][k] (64 MB)
__device__ float g_hT[2][2][H_][B_];                 // h transposed: [phase][dir][j][b]
__device__ float g_cT[2][H_][B_];                    // c transposed: [dir][j][b]

// ---------------------------------------------------------------------------
// PTX helpers
// ---------------------------------------------------------------------------
__device__ __forceinline__ void fma2(u64& c, u64 a, u64 b) {
    asm volatile("fma.rn.f32x2 %0, %1, %2, %0;" : "+l"(c) : "l"(a), "l"(b));
}
__device__ __forceinline__ u64 rep2(float x) {
    u64 r;
    asm volatile("mov.b64 %0, {%1, %1};" : "=l"(r) : "f"(x));
    return r;
}
__device__ __forceinline__ void cp_async16(u32 smem_addr, const void* gptr) {
    asm volatile("cp.async.cg.shared.global [%0], [%1], 16;" :: "r"(smem_addr), "l"(gptr));
}
__device__ __forceinline__ void cp_commit()  { asm volatile("cp.async.commit_group;"); }
__device__ __forceinline__ void cp_wait1()   { asm volatile("cp.async.wait_group 1;"); }
__device__ __forceinline__ void cp_wait0()   { asm volatile("cp.async.wait_group 0;"); }

__device__ __forceinline__ float lo32(u64 v) { return __uint_as_float((u32)(v & 0xffffffffull)); }
__device__ __forceinline__ float hi32(u64 v) { return __uint_as_float((u32)(v >> 32)); }

// ---------------------------------------------------------------------------
// Init: zero h(phase 0) and c
// ---------------------------------------------------------------------------
__global__ void init_state_kernel() {
    int i = blockIdx.x * blockDim.x + threadIdx.x;
    if (i < 2 * BH) {
        ((float*)g_hT)[i] = 0.0f;
        ((float*)g_cT)[i] = 0.0f;
    }
}

// ---------------------------------------------------------------------------
// Transpose + duplicate w_hh [4096,1024] -> g_wTd [dir][1024][8192]
// ---------------------------------------------------------------------------
__global__ void __launch_bounds__(256) transpose_w_kernel(
    const float* __restrict__ wfw, const float* __restrict__ wbw)
{
    __shared__ float tile[32][33];
    const int dir = blockIdx.z;
    const float* w = dir ? wbw : wfw;
    const int n0 = blockIdx.x * 32;
    const int k0 = blockIdx.y * 32;
    const int tx = threadIdx.x & 31, ty = threadIdx.x >> 5;
#pragma unroll
    for (int r = 0; r < 32; r += 8)
        tile[ty + r][tx] = w[(size_t)(n0 + ty + r) * H_ + k0 + tx];
    __syncthreads();
#pragma unroll
    for (int r = 0; r < 32; r += 8) {
        float v = tile[tx][ty + r];
        *(float2*)&g_wTd[dir][k0 + ty + r][2 * (n0 + tx)] = make_float2(v, v);
    }
}

// ---------------------------------------------------------------------------
// Input projection (f32x2): xp = x @ w_ih^T + (b_ih + b_hh)
// ---------------------------------------------------------------------------
__global__ void __launch_bounds__(128) input_proj_kernel(
    const float* __restrict__ x,
    const float* __restrict__ w_fw, const float* __restrict__ w_bw,
    const float* __restrict__ bi_fw, const float* __restrict__ bh_fw,
    const float* __restrict__ bi_bw, const float* __restrict__ bh_bw)
{
    const int gt  = blockIdx.x;
    const int t   = blockIdx.y;
    const int dir = blockIdx.z;

    const float* w     = dir ? w_bw : w_fw;
    const float* bi    = dir ? bi_bw : bi_fw;
    const float* bh    = dir ? bh_bw : bh_fw;
    const int    src_t = dir ? (T_ - 1 - t) : t;

    __shared__ float sA[16][68];
    __shared__ float sB[16][68];

    const int tid = threadIdx.x;
    const int tr  = tid >> 4;
    const int tc  = tid & 15;

    u64 acc[4][4];
#pragma unroll
    for (int p = 0; p < 4; p++)
#pragma unroll
        for (int j = 0; j < 4; j++) acc[p][j] = 0ull;

    const float* Abase = x + (size_t)src_t * I_;
    const float* Bbase = w + (size_t)(gt * 64) * I_;

    for (int k0 = 0; k0 < I_; k0 += 16) {
#pragma unroll 4
        for (int idx = tid; idx < 1024; idx += 128) {
            int kk = idx & 15, m = idx >> 4;
            sA[kk][m] = Abase[(size_t)m * (T_ * I_) + k0 + kk];
        }
#pragma unroll 4
        for (int idx = tid; idx < 1024; idx += 128) {
            int kk = idx & 15, n = idx >> 4;
            sB[kk][n] = Bbase[(size_t)n * I_ + k0 + kk];
        }
        __syncthreads();
#pragma unroll
        for (int kk = 0; kk < 16; kk++) {
            const float* ap = &sA[kk][tr * 8];
            u64 a0 = *(const u64*)(ap + 0);
            u64 a1 = *(const u64*)(ap + 2);
            u64 a2 = *(const u64*)(ap + 4);
            u64 a3 = *(const u64*)(ap + 6);
            float4 b4 = *(const float4*)&sB[kk][tc * 4];
            u64 b0 = rep2(b4.x), b1 = rep2(b4.y), b2 = rep2(b4.z), b3 = rep2(b4.w);
            fma2(acc[0][0], a0, b0); fma2(acc[0][1], a0, b1); fma2(acc[0][2], a0, b2); fma2(acc[0][3], a0, b3);
            fma2(acc[1][0], a1, b0); fma2(acc[1][1], a1, b1); fma2(acc[1][2], a1, b2); fma2(acc[1][3], a1, b3);
            fma2(acc[2][0], a2, b0); fma2(acc[2][1], a2, b1); fma2(acc[2][2], a2, b2); fma2(acc[2][3], a2, b3);
            fma2(acc[3][0], a3, b0); fma2(acc[3][1], a3, b1); fma2(acc[3][2], a3, b2); fma2(acc[3][3], a3, b3);
        }
        __syncthreads();
    }

    const int gbase = gt * 64 + tc * 4;
    float bias[4];
#pragma unroll
    for (int j = 0; j < 4; j++) bias[j] = bi[gbase + j] + bh[gbase + j];

    float* outp = g_xp + (((size_t)dir * T_ + t) * B_) * G4;
#pragma unroll
    for (int i = 0; i < 8; i++) {
        int m = tr * 8 + i;
        int p = i >> 1;
        float v0 = (i & 1) ? hi32(acc[p][0]) : lo32(acc[p][0]);
        float v1 = (i & 1) ? hi32(acc[p][1]) : lo32(acc[p][1]);
        float v2 = (i & 1) ? hi32(acc[p][2]) : lo32(acc[p][2]);
        float v3 = (i & 1) ? hi32(acc[p][3]) : lo32(acc[p][3]);
        float4 v = make_float4(v0 + bias[0], v1 + bias[1], v2 + bias[2], v3 + bias[3]);
        *(float4*)(outp + (size_t)m * G4 + gbase) = v;
    }
}

// ---------------------------------------------------------------------------
// LSTM step. CTA=(dir,jt): 64x64 tile, K=1024, 256 threads (8 warps),
// BK=32, 3-stage cp.async ring (1 sync/stage), duplicated-B f32x2 math.
// Dynamic smem layout: sA[3][32*64] | sB[3][32*128] | sG[64*68]
// ---------------------------------------------------------------------------
#define SA_FLOATS (3 * BK * 64)       // 6144
#define SB_FLOATS (3 * BK * 128)      // 12288
#define SG_FLOATS (64 * 68)           // 4352
#define STEP_SMEM_BYTES ((SA_FLOATS + SB_FLOATS + SG_FLOATS) * 4)

struct StageCtx {
    u32 sA_u, sB_u;
    const float* hT;
    const float* wTd;
    int jt, tid;
};

__device__ __forceinline__ void issue_stage(const StageCtx& cx, int s) {
    const int k0  = s * BK;
    const int buf = s % 3;
    const u32 a_dst = cx.sA_u + (u32)(buf * BK * 64 * 4);
    const u32 b_dst = cx.sB_u + (u32)(buf * BK * 128 * 4);
    // A: 2048 floats contiguous from hT + k0*64
    cp_async16(a_dst + cx.tid * 16,        cx.hT + k0 * 64 + cx.tid * 4);
    cp_async16(a_dst + cx.tid * 16 + 4096, cx.hT + k0 * 64 + 1024 + cx.tid * 4);
    // B: 4096 dup-floats: per kk, 4 gate runs of 32 dup-floats
#pragma unroll
    for (int h = 0; h < 4; h++) {
        int c = cx.tid + h * 256;
        int kk = c >> 5, piece = c & 31;
        int q = piece >> 3, sub = piece & 7;
        cp_async16(b_dst + (u32)((kk * 128 + q * 32 + sub * 4) * 4),
                   cx.wTd + (size_t)(k0 + kk) * (2 * G4) + 2 * (q * H_ + cx.jt * 16) + sub * 4);
    }
    cp_commit();
}

__global__ void __launch_bounds__(256) lstm_step_kernel(float* __restrict__ out, int t)
{
    extern __shared__ float smem[];
    float* sA = smem;
    float* sB = smem + SA_FLOATS;
    float* sG = smem + SA_FLOATS + SB_FLOATS;

    const int bx  = blockIdx.x;    // 0..127
    const int dir = bx & 1;
    const int jt  = bx >> 1;       // 0..63

    const int    phase = t & 1;
    const float* hT    = &g_hT[phase][dir][0][0];
    float*       hTn   = &g_hT[phase ^ 1][dir][0][0];
    float*       cT    = &g_cT[dir][0][0];
    const float* wTd   = &g_wTd[dir][0][0];
    const float* xp    = g_xp + ((size_t)dir * T_ + t) * B_ * G4;

    const int tid  = threadIdx.x;
    const int wid  = tid >> 5;     // 0..7 -> b rows wid*8..+7
    const int lane = tid & 31;     // cols 2*lane, 2*lane+1

    StageCtx cx;
    cx.sA_u = (u32)__cvta_generic_to_shared(sA);
    cx.sB_u = (u32)__cvta_generic_to_shared(sB);
    cx.hT = hT; cx.wTd = wTd; cx.jt = jt; cx.tid = tid;

    u64 acc[4][2];
#pragma unroll
    for (int p = 0; p < 4; p++) { acc[p][0] = 0ull; acc[p][1] = 0ull; }

    issue_stage(cx, 0);
    issue_stage(cx, 1);

    for (int s = 0; s < NSTAGE; s++) {
        if (s < NSTAGE - 1) cp_wait1(); else cp_wait0();
        __syncthreads();                       // all threads' stage-s data visible;
                                               // all done computing s-1 -> safe to refill
        if (s + 2 < NSTAGE) issue_stage(cx, s + 2);

        const float* A  = sA + (s % 3) * (BK * 64) + wid * 8;
        const float* Bm = sB + (s % 3) * (BK * 128) + lane * 4;
#pragma unroll
        for (int kk = 0; kk < BK; kk++) {
            const float* ap = A + kk * 64;     // warp-uniform -> LDS broadcast
            u64 a0 = *(const u64*)(ap + 0);
            u64 a1 = *(const u64*)(ap + 2);
            u64 a2 = *(const u64*)(ap + 4);
            u64 a3 = *(const u64*)(ap + 6);
            const float* bp = Bm + kk * 128;
            u64 b0 = *(const u64*)(bp + 0);    // (w[c0], w[c0]) pre-duplicated
            u64 b1 = *(const u64*)(bp + 2);    // (w[c1], w[c1])
            fma2(acc[0][0], a0, b0); fma2(acc[0][1], a0, b1);
            fma2(acc[1][0], a1, b0); fma2(acc[1][1], a1, b1);
            fma2(acc[2][0], a2, b0); fma2(acc[2][1], a2, b1);
            fma2(acc[3][0], a3, b0); fma2(acc[3][1], a3, b1);
        }
    }

    // ---- stage gates (+xp) into sG[64][68] ----
    {
        const int c0   = 2 * lane;             // local col (even)
        const int q    = c0 >> 4;
        const int jj   = c0 & 15;
        const int gcol = q * H_ + jt * 16 + jj;
#pragma unroll
        for (int i = 0; i < 8; i++) {
            int m = wid * 8 + i;
            int p = i >> 1;
            float v0 = (i & 1) ? hi32(acc[p][0]) : lo32(acc[p][0]);
            float v1 = (i & 1) ? hi32(acc[p][1]) : lo32(acc[p][1]);
            float2 xv = *(const float2*)(xp + (size_t)m * G4 + gcol);
            sG[m * 68 + c0]     = v0 + xv.x;
            sG[m * 68 + c0 + 1] = v1 + xv.y;
        }
    }
    __syncthreads();

    // ---- activation + state update ----
#pragma unroll
    for (int p4 = tid; p4 < 1024; p4 += 256) {
        int b = p4 >> 4, j = p4 & 15;
        float ig = sG[b * 68 + j];
        float fg = sG[b * 68 + 16 + j];
        float gg = sG[b * 68 + 32 + j];
        float og = sG[b * 68 + 48 + j];
        int jc = jt * 16 + j;

        float c_old = cT[jc * B_ + b];
        float si = 1.0f / (1.0f + __expf(-ig));
        float sf = 1.0f / (1.0f + __expf(-fg));
        float so = 1.0f / (1.0f + __expf(-og));
        float cn = sf * c_old + si * tanhf(gg);
        float hn = so * tanhf(cn);

        cT[jc * B_ + b]  = cn;
        hTn[jc * B_ + b] = hn;
        out[((size_t)b * T_ + t) * (2 * H_) + dir * H_ + jc] = hn;
    }
}

// ---------------------------------------------------------------------------
// Finalize: [h_fw | c_fw | h_bw | c_bw], each [B, H]; final h in phase 0
// ---------------------------------------------------------------------------
__global__ void finalize_kernel(float* __restrict__ out) {
    int i = blockIdx.x * blockDim.x + threadIdx.x;
    if (i >= BH) return;
    int b = i >> 10, j = i & 1023;
    const size_t base = (size_t)B_ * T_ * 2 * H_;
    out[base + 0 * (size_t)BH + i] = g_hT[0][0][j][b];
    out[base + 1 * (size_t)BH + i] = g_cT[0][j][b];
    out[base + 2 * (size_t)BH + i] = g_hT[0][1][j][b];
    out[base + 3 * (size_t)BH + i] = g_cT[1][j][b];
}

// ---------------------------------------------------------------------------
// Launch
// ---------------------------------------------------------------------------
extern "C" void kernel_launch(void* const* d_in, const int* in_sizes, int n_in,
                              void* d_out, int out_size) {
    (void)in_sizes; (void)n_in; (void)out_size;
    const float* x       = (const float*)d_in[0];
    const float* w_ih_fw = (const float*)d_in[1];
    const float* w_hh_fw = (const float*)d_in[2];
    const float* b_ih_fw = (const float*)d_in[3];
    const float* b_hh_fw = (const float*)d_in[4];
    const float* w_ih_bw = (const float*)d_in[5];
    const float* w_hh_bw = (const float*)d_in[6];
    const float* b_ih_bw = (const float*)d_in[7];
    const float* b_hh_bw = (const float*)d_in[8];
    float* out = (float*)d_out;

    cudaFuncSetAttribute(lstm_step_kernel,
                         cudaFuncAttributeMaxDynamicSharedMemorySize,
                         STEP_SMEM_BYTES);

    init_state_kernel<<<(2 * BH + 255) / 256, 256>>>();

    dim3 gtw(G4 / 32, H_ / 32, 2);
    transpose_w_kernel<<<gtw, 256>>>(w_hh_fw, w_hh_bw);

    dim3 gproj(64, T_, 2);
    input_proj_kernel<<<gproj, 128>>>(x, w_ih_fw, w_ih_bw,
                                      b_ih_fw, b_hh_fw, b_ih_bw, b_hh_bw);

    for (int t = 0; t < T_; t++) {
        lstm_step_kernel<<<128, 256, STEP_SMEM_BYTES>>>(out, t);
    }

    finalize_kernel<<<(BH + 255) / 256, 256>>>(out);
}